// round 17
// baseline (speedup 1.0000x reference)
#include <cuda_runtime.h>
#include <cuda_bf16.h>
#include <cstdint>

// Problem constants
#define NB   64      // batch
#define SEQ  785     // tokens
#define SEQ_PAD 832  // padded key stride for V rows (16B-aligned cp.async chunks)
#define CDIM 768     // channels
#define NH   12      // heads
#define HD   64      // head dim
#define NLOC 78      // num_local = int(0.1 * 784)

// ---------------- device scratch (static, no allocations) ----------------
__device__ __nv_bfloat16 g_Kbf[(size_t)NB * NH * SEQ * HD];      // [b][h][n][d]
__device__ __nv_bfloat16 g_Vbf[(size_t)NB * NH * HD * SEQ_PAD];  // [b][h][d][n] transposed, zero-padded
__device__ __nv_bfloat16 g_Qbf[(size_t)NB * NH * NLOC * HD];     // [b][h][j][d]
__device__ float g_att[(size_t)NB * NLOC * CDIM];                // [b*78][768]
__device__ int   g_idx[NB * NLOC];                               // gathered token index (1..784)
__device__ __nv_bfloat16 g_x_bf[(size_t)NB * SEQ * CDIM];        // x in bf16
__device__ __nv_bfloat16 g_Wkv_bt[2 * CDIM * CDIM];              // Wkv^T [1536][768] bf16
__device__ __nv_bfloat16 g_Wq_bt[CDIM * CDIM];                   // Wq^T  [768][768] bf16

// ---------------- top-k by exact rank (matches jax.lax.top_k ties) -------
__global__ __launch_bounds__(1024) void topk_kernel(const float* __restrict__ roll)
{
    int b = blockIdx.x;
    __shared__ float v[SEQ - 1];  // 784
    const float* src = roll + (size_t)b * SEQ * SEQ + 1;  // row 0, cols 1..784
    for (int i = threadIdx.x; i < SEQ - 1; i += 1024) v[i] = src[i];
    __syncthreads();
    for (int i = threadIdx.x; i < SEQ - 1; i += 1024) {
        float vi = v[i];
        int rank = 0;
        for (int j = 0; j < SEQ - 1; j++) {
            float vj = v[j];
            rank += (vj > vi) || (vj == vi && j < i);
        }
        if (rank < NLOC) g_idx[b * NLOC + rank] = i + 1;
    }
}

// ---------------- fused: out = x (copy) ; g_x_bf = bf16(x) ----------------
__global__ __launch_bounds__(256) void copyconv_x_kernel(const float* __restrict__ src,
                                                         float* __restrict__ out)
{
    size_t n4 = (size_t)NB * SEQ * CDIM / 4;
    size_t stride = (size_t)gridDim.x * blockDim.x;
    for (size_t i = (size_t)blockIdx.x * blockDim.x + threadIdx.x; i < n4; i += stride) {
        float4 v = *(const float4*)(src + i * 4);
        *(float4*)(out + i * 4) = v;
        __nv_bfloat16 o[4];
        o[0] = __float2bfloat16_rn(v.x);
        o[1] = __float2bfloat16_rn(v.y);
        o[2] = __float2bfloat16_rn(v.z);
        o[3] = __float2bfloat16_rn(v.w);
        *(uint2*)(g_x_bf + i * 4) = *(uint2*)o;
    }
}

// ---------------- transpose+convert: src fp32 [R][C] -> dst bf16 [C][R] ---
__global__ void convt_kernel(const float* __restrict__ src,
                             __nv_bfloat16* __restrict__ dst, int R, int C)
{
    __shared__ float t[32][33];
    int c0 = blockIdx.x * 32, r0 = blockIdx.y * 32;
    int x = threadIdx.x, y = threadIdx.y;   // 32 x 8
    for (int i = y; i < 32; i += 8) t[i][x] = src[(size_t)(r0 + i) * C + c0 + x];
    __syncthreads();
    for (int i = y; i < 32; i += 8)
        dst[(size_t)(c0 + i) * R + r0 + x] = __float2bfloat16_rn(t[x][i]);
}

// ---------------- helpers --------------------------------------------------
__device__ __forceinline__ uint32_t packbf(float lo, float hi) {
    uint32_t u;
    asm("cvt.rn.bf16x2.f32 %0, %1, %2;" : "=r"(u) : "f"(hi), "f"(lo));
    return u;
}

#define MMA_TF32(C, A, B)                                                     \
    asm volatile(                                                             \
        "mma.sync.aligned.m16n8k8.row.col.f32.tf32.tf32.f32 "                 \
        "{%0,%1,%2,%3}, {%4,%5,%6,%7}, {%8,%9}, {%0,%1,%2,%3};"               \
        : "+f"((C)[0]), "+f"((C)[1]), "+f"((C)[2]), "+f"((C)[3])              \
        : "r"((A)[0]), "r"((A)[1]), "r"((A)[2]), "r"((A)[3]),                 \
          "r"((B)[0]), "r"((B)[1]))

#define MMA_BF16(C, A, B)                                                     \
    asm volatile(                                                             \
        "mma.sync.aligned.m16n8k16.row.col.f32.bf16.bf16.f32 "                \
        "{%0,%1,%2,%3}, {%4,%5,%6,%7}, {%8,%9}, {%0,%1,%2,%3};"               \
        : "+f"((C)[0]), "+f"((C)[1]), "+f"((C)[2]), "+f"((C)[3])              \
        : "r"((A)[0]), "r"((A)[1]), "r"((A)[2]), "r"((A)[3]),                 \
          "r"((B)[0]), "r"((B)[1]))

#define LDSM_X4(r, a)                                                         \
    asm volatile("ldmatrix.sync.aligned.m8n8.x4.shared.b16 {%0,%1,%2,%3}, [%4];" \
        : "=r"((r)[0]), "=r"((r)[1]), "=r"((r)[2]), "=r"((r)[3]) : "r"(a))

__device__ __forceinline__ void cp16(uint32_t s, const void* g) {
    asm volatile("cp.async.cg.shared.global [%0], [%1], 16;" :: "r"(s), "l"(g));
}
#define CP_COMMIT()  asm volatile("cp.async.commit_group;")
#define CP_WAIT(n)   asm volatile("cp.async.wait_group %0;" :: "n"(n))

// ---------------- unified bf16 GEMM, 256x128x32, 64x64 warp tile ----------
// 8 warps in 4(M) x 2(N); 3-stage cp.async; 1 CTA/SM.
// MODE 0: A = g_x_bf direct, B = g_Wkv_bt, epilogue -> g_Kbf / g_Vbf (N=1536)
// MODE 1: A = g_x_bf gathered rows, B = g_Wq_bt, epilogue -> g_Qbf   (N=768)
#define BF_ROWB   80                              // bytes per smem row (32bf16+pad)
#define BF_AREA_A (256 * BF_ROWB)                 // 20480 bytes
#define BF_AREA_B (128 * BF_ROWB)                 // 10240 bytes
#define BF_STAGEB (BF_AREA_A + BF_AREA_B)         // 30720 bytes per stage
#define BF_ST     3
#define BF_SMEM_BYTES (BF_ST * BF_STAGEB)         // 92160

template <int MODE>
__global__ __launch_bounds__(256) void gemm_bf16(const float* __restrict__ bias)
{
    const int M = (MODE == 0) ? NB * SEQ : NB * NLOC;
    const int K = CDIM;
    const int BK = 32;
    extern __shared__ __nv_bfloat16 smb[];
    uint32_t smem_u32 = (uint32_t)__cvta_generic_to_shared(smb);

    int t = threadIdx.x;
    int wid = t >> 5, lane = t & 31;
    int warp_m = wid & 3, warp_n = wid >> 2;   // 4 x 2
    int g = lane >> 2, tig = lane & 3;
    int sel = lane >> 3, lrow = lane & 7;
    int bc = blockIdx.x, br = blockIdx.y;

    const __nv_bfloat16* Wsrc = (MODE == 0) ? g_Wkv_bt : g_Wq_bt;

    // loaders: A 256 rows x 4 chunks = 4 tasks/thread; B 128 x 4 = 2 tasks
    const __nv_bfloat16* arow[4];
    uint32_t asoff[4];
#pragma unroll
    for (int p = 0; p < 4; p++) {
        int task = p * 256 + t;
        int r = task >> 2, ch = task & 3;
        int am = br * 256 + r;
        int cm = am < M ? am : M - 1;
        if (MODE == 1) {
            int bb2 = cm / NLOC;
            arow[p] = g_x_bf + ((size_t)(bb2 * SEQ + g_idx[cm])) * K + ch * 8;
        } else {
            arow[p] = g_x_bf + (size_t)cm * K + ch * 8;
        }
        asoff[p] = (uint32_t)(r * BF_ROWB + ch * 16);
    }
    const __nv_bfloat16* brow[2];
    uint32_t bsoff[2];
#pragma unroll
    for (int p = 0; p < 2; p++) {
        int task = p * 256 + t;
        int r = task >> 2, ch = task & 3;
        int bn = bc * 128 + r;
        brow[p] = Wsrc + (size_t)bn * K + ch * 8;
        bsoff[p] = (uint32_t)(BF_AREA_A + r * BF_ROWB + ch * 16);
    }

    // prologue: stages 0,1
#pragma unroll
    for (int s = 0; s < 2; s++) {
        uint32_t sb = smem_u32 + s * BF_STAGEB;
#pragma unroll
        for (int p = 0; p < 4; p++) cp16(sb + asoff[p], arow[p] + s * BK);
#pragma unroll
        for (int p = 0; p < 2; p++) cp16(sb + bsoff[p], brow[p] + s * BK);
        CP_COMMIT();
    }

    float acc[4][8][4];
#pragma unroll
    for (int i = 0; i < 4; i++)
#pragma unroll
        for (int j = 0; j < 8; j++)
#pragma unroll
            for (int c = 0; c < 4; c++) acc[i][j][c] = 0.f;

    // per-thread ldmatrix base offsets (within stage)
    uint32_t a_off = (uint32_t)((warp_m * 64 + (sel & 1) * 8 + lrow) * BF_ROWB
                                + (sel >> 1) * 16);
    uint32_t b_off = (uint32_t)(BF_AREA_A
                                + (warp_n * 64 + (sel >> 1) * 8 + lrow) * BF_ROWB
                                + (sel & 1) * 16);

    const int nk = K / BK;   // 24
    int st = 0;
    for (int kt = 0; kt < nk; kt++) {
        CP_WAIT(1);
        __syncthreads();

        int nxt = kt + 2;
        if (nxt < nk) {
            uint32_t sb = smem_u32 + (nxt % BF_ST) * BF_STAGEB;
#pragma unroll
            for (int p = 0; p < 4; p++) cp16(sb + asoff[p], arow[p] + nxt * BK);
#pragma unroll
            for (int p = 0; p < 2; p++) cp16(sb + bsoff[p], brow[p] + nxt * BK);
        }
        CP_COMMIT();

        uint32_t sb = smem_u32 + st * BF_STAGEB;
        uint32_t ab = sb + a_off;
        uint32_t bb = sb + b_off;

#pragma unroll
        for (int ks = 0; ks < 2; ks++) {    // two k16 steps
            uint32_t af[4][4], bf[8][2];
#pragma unroll
            for (int i = 0; i < 4; i++)
                LDSM_X4(af[i], ab + i * (16 * BF_ROWB) + ks * 32);
#pragma unroll
            for (int jp = 0; jp < 4; jp++) {
                uint32_t bt[4];
                LDSM_X4(bt, bb + jp * (16 * BF_ROWB) + ks * 32);
                bf[2 * jp][0] = bt[0]; bf[2 * jp][1] = bt[1];
                bf[2 * jp + 1][0] = bt[2]; bf[2 * jp + 1][1] = bt[3];
            }
#pragma unroll
            for (int i = 0; i < 4; i++)
#pragma unroll
                for (int j = 0; j < 8; j++)
                    MMA_BF16(acc[i][j], af[i], bf[j]);
        }
        st = (st + 1 == BF_ST) ? 0 : st + 1;
    }

    // epilogue: bf16 outputs (K/Q packed u32; V transposed scalar)
#pragma unroll
    for (int i = 0; i < 4; i++) {
        int mbase = br * 256 + warp_m * 64 + i * 16 + g;
#pragma unroll
        for (int half = 0; half < 2; half++) {
            int m = mbase + half * 8;
            if (m >= M) continue;
            if (MODE == 0) {
                int bb2 = m / SEQ, nn = m % SEQ;
#pragma unroll
                for (int j = 0; j < 8; j++) {
                    int n0 = bc * 128 + warp_n * 64 + j * 8 + 2 * tig;
                    float v0 = acc[i][j][half * 2 + 0] + bias[n0];
                    float v1 = acc[i][j][half * 2 + 1] + bias[n0 + 1];
                    if (n0 < CDIM) {
                        int h = n0 >> 6, d = n0 & 63;   // d even
                        uint32_t* dst = (uint32_t*)g_Kbf
                            + (((size_t)bb2 * NH + h) * SEQ + nn) * (HD / 2) + d / 2;
                        *dst = packbf(v0, v1);
                    } else {
                        int nc = n0 - CDIM;
                        int h = nc >> 6, d = nc & 63;
                        __nv_bfloat16* dst = g_Vbf
                            + (((size_t)bb2 * NH + h) * HD + d) * SEQ_PAD + nn;
                        dst[0]       = __float2bfloat16_rn(v0);
                        dst[SEQ_PAD] = __float2bfloat16_rn(v1);
                    }
                }
            } else {
                int bb2 = m / NLOC, jj = m % NLOC;
#pragma unroll
                for (int j = 0; j < 8; j++) {
                    int n0 = bc * 128 + warp_n * 64 + j * 8 + 2 * tig;
                    float v0 = acc[i][j][half * 2 + 0] + bias[n0];
                    float v1 = acc[i][j][half * 2 + 1] + bias[n0 + 1];
                    int h = n0 >> 6, d = n0 & 63;
                    uint32_t* dst = (uint32_t*)g_Qbf
                        + (((size_t)bb2 * NH + h) * NLOC + jj) * (HD / 2) + d / 2;
                    *dst = packbf(v0, v1);
                }
            }
        }
    }
}

// ---------------- TF32 GEMM (out projection only), 128x128x16 -------------
#define G_APAD 20
#define G_BPAD 136
#define G_AFL  (128 * G_APAD)
#define G_BFL  (16 * G_BPAD)
#define G_STG  (G_AFL + G_BFL)
#define G_ST   3
#define G_SMEM_BYTES (G_ST * G_STG * 4)

__global__ __launch_bounds__(256, 2) void gemm_tf32_out(
    const float* __restrict__ B, const float* __restrict__ bias,
    float* __restrict__ C)
{
    const int M = NB * NLOC, N = CDIM, K = CDIM;
    const int BM = 128, BN = 128, BK = 16;
    extern __shared__ float sm[];
    uint32_t smem_u32 = (uint32_t)__cvta_generic_to_shared(sm);

    int tid = threadIdx.x;
    int wid = tid >> 5, lane = tid & 31;
    int warp_m = wid & 1, warp_n = wid >> 1;
    int g = lane >> 2, tig = lane & 3;

    int bc = blockIdx.x, br = blockIdx.y;

    const float* Ap = (const float*)g_att;

    int ar  = tid >> 2;
    int acl = (tid & 3) * 4;
    int am0 = br * BM + ar;
    int am1 = am0 + 64;
    int cm0 = am0 < M ? am0 : M - 1;
    int cm1 = am1 < M ? am1 : M - 1;
    const float* Arow0 = Ap + (size_t)cm0 * K + acl;
    const float* Arow1 = Ap + (size_t)cm1 * K + acl;

    int brw = tid >> 5;
    int bcl = (tid & 31) * 4;
    const float* Bp0 = B + (size_t)brw * N + bc * BN + bcl;
    const float* Bp1 = Bp0 + (size_t)8 * N;

    uint32_t sA = smem_u32 + (uint32_t)(ar * G_APAD + acl) * 4;
    uint32_t sB = smem_u32 + (uint32_t)(G_AFL + brw * G_BPAD + bcl) * 4;

    int nk = K / BK;

#pragma unroll
    for (int p = 0; p < G_ST - 1; p++) {
        uint32_t so = (uint32_t)(p * G_STG) * 4;
        cp16(sA + so, Arow0 + p * BK);
        cp16(sA + so + 64 * G_APAD * 4, Arow1 + p * BK);
        cp16(sB + so, Bp0 + (size_t)p * BK * N);
        cp16(sB + so + 8 * G_BPAD * 4, Bp1 + (size_t)p * BK * N);
        CP_COMMIT();
    }

    float acc[4][4][4];
#pragma unroll
    for (int i = 0; i < 4; i++)
#pragma unroll
        for (int j = 0; j < 4; j++)
#pragma unroll
            for (int c = 0; c < 4; c++) acc[i][j][c] = 0.f;

    int st = 0;
    for (int kt = 0; kt < nk; kt++) {
        CP_WAIT(G_ST - 2);
        __syncthreads();

        int nxt = kt + G_ST - 1;
        if (nxt < nk) {
            int stn = nxt % G_ST;
            uint32_t so = (uint32_t)(stn * G_STG) * 4;
            cp16(sA + so, Arow0 + nxt * BK);
            cp16(sA + so + 64 * G_APAD * 4, Arow1 + nxt * BK);
            cp16(sB + so, Bp0 + (size_t)nxt * BK * N);
            cp16(sB + so + 8 * G_BPAD * 4, Bp1 + (size_t)nxt * BK * N);
        }
        CP_COMMIT();

        const float* As = sm + st * G_STG;
        const float* Bs = As + G_AFL;

#pragma unroll
        for (int ks = 0; ks < 2; ks++) {
            int k0 = ks * 8;
            uint32_t af[4][4];
            uint32_t bf[4][2];
#pragma unroll
            for (int i = 0; i < 4; i++) {
                int r = warp_m * 64 + i * 16 + g;
                af[i][0] = __float_as_uint(As[r * G_APAD + k0 + tig]);
                af[i][1] = __float_as_uint(As[(r + 8) * G_APAD + k0 + tig]);
                af[i][2] = __float_as_uint(As[r * G_APAD + k0 + tig + 4]);
                af[i][3] = __float_as_uint(As[(r + 8) * G_APAD + k0 + tig + 4]);
            }
#pragma unroll
            for (int j = 0; j < 4; j++) {
                int cix = warp_n * 32 + j * 8 + g;
                bf[j][0] = __float_as_uint(Bs[(k0 + tig) * G_BPAD + cix]);
                bf[j][1] = __float_as_uint(Bs[(k0 + tig + 4) * G_BPAD + cix]);
            }
#pragma unroll
            for (int i = 0; i < 4; i++)
#pragma unroll
                for (int j = 0; j < 4; j++)
                    MMA_TF32(acc[i][j], af[i], bf[j]);
        }
        st = (st + 1 == G_ST) ? 0 : st + 1;
    }

#pragma unroll
    for (int i = 0; i < 4; i++) {
        int mbase = br * BM + warp_m * 64 + i * 16 + g;
#pragma unroll
        for (int half = 0; half < 2; half++) {
            int m = mbase + half * 8;
            if (m >= M) continue;
            int bb = m / NLOC;
            int row = bb * SEQ + g_idx[m];
            float* crow = C + (size_t)row * CDIM;
#pragma unroll
            for (int j = 0; j < 4; j++) {
                int n0 = bc * BN + warp_n * 32 + j * 8 + 2 * tig;
                crow[n0]     = acc[i][j][half * 2 + 0] + bias[n0];
                crow[n0 + 1] = acc[i][j][half * 2 + 1] + bias[n0 + 1];
            }
        }
    }
}

// ---------------- bf16 tensor-core flash attention per (b,h) --------------
// M=96 (78 valid), key tile 64, 8 warps 2x4; double-buffered K/V via cp.async.
#define AT_M   96
#define AT_KN  64
#define AT_NT  13                          // ceil(785/64)
#define QK_PW  36                          // row pitch in u32 words (32 data + 4 pad)
// u32-unit offsets in dynamic smem
#define AOFF_Q   0                         // Qs bf16 [96][72]   -> 3456 u32
#define AOFF_K0  3456                      // Ks buf0 [64][72]   -> 2304
#define AOFF_V0  (AOFF_K0 + 2304)          // Vs buf0 [64][72]   -> 2304
#define AOFF_K1  (AOFF_V0 + 2304)          // Ks buf1
#define AOFF_V1  (AOFF_K1 + 2304)          // Vs buf1
#define AOFF_S   (AOFF_V1 + 2304)          // Ss fp32 [96][68]   -> 6528
#define AOFF_P   (AOFF_S + 6528)           // Ps bf16 [96][72]   -> 3456 u32
#define AOFF_M   (AOFF_P + 3456)
#define AOFF_L   (AOFF_M + AT_M)
#define AOFF_F   (AOFF_L + AT_M)
#define AT_SMEM_U32 (AOFF_F + AT_M)        // 22944 u32 = 91776 B

__global__ __launch_bounds__(256, 2) void attn_kernel()
{
    extern __shared__ float sm[];
    uint32_t* smu = (uint32_t*)sm;
    uint32_t* Qs_u = smu + AOFF_Q;
    float*    Ss   = sm + AOFF_S;
    uint32_t* Ps_u = smu + AOFF_P;
    float* s_m = sm + AOFF_M;
    float* s_l = sm + AOFF_L;
    float* s_f = sm + AOFF_F;

    uint32_t smem_base = (uint32_t)__cvta_generic_to_shared(sm);
    const uint32_t kbase[2] = { smem_base + AOFF_K0 * 4, smem_base + AOFF_K1 * 4 };
    const uint32_t vbase[2] = { smem_base + AOFF_V0 * 4, smem_base + AOFF_V1 * 4 };

    int bh = blockIdx.x;
    int b = bh / NH, h = bh % NH;
    int t = threadIdx.x;
    int wid = t >> 5, lane = t & 31;
    int warp_m = wid & 1, warp_n = wid >> 1;   // 2 x 4
    int g = lane >> 2, tig = lane & 3;

    const __nv_bfloat16* qsrc = g_Qbf + (size_t)bh * NLOC * HD;
    const __nv_bfloat16* ksrc = g_Kbf + (size_t)bh * SEQ * HD;
    const __nv_bfloat16* vsrc = g_Vbf + (size_t)bh * HD * SEQ_PAD;

    // per-thread K/V load tasks: 2 rows x 1 chunk each pass (64*8/256 = 2)
    int kv_r0 = t >> 3, kv_ch = t & 7;        // rows kv_r0, kv_r0+32

    // prologue: cp.async tile 0 into buf 0
    {
        int n0 = 0;
#pragma unroll
        for (int p = 0; p < 2; p++) {
            int r = kv_r0 + p * 32;
            int src = n0 + r; if (src > SEQ - 1) src = SEQ - 1;
            cp16(kbase[0] + (uint32_t)(r * QK_PW * 4 + kv_ch * 16), ksrc + src * HD + kv_ch * 8);
            cp16(vbase[0] + (uint32_t)(r * QK_PW * 4 + kv_ch * 16),
                 vsrc + r * SEQ_PAD + n0 + kv_ch * 8);
        }
        CP_COMMIT();
    }

    // load Q (raw bf16), zero rows 78..95
    for (int l = t; l < AT_M * 8; l += 256) {
        int r = l >> 3, ch = l & 7;
        uint4 v = make_uint4(0, 0, 0, 0);
        if (r < NLOC) v = *(const uint4*)(qsrc + r * HD + ch * 8);
        *(uint4*)&Qs_u[r * QK_PW + ch * 4] = v;
    }
    if (t < AT_M) { s_m[t] = -1e30f; s_l[t] = 0.f; }

    float acc_o[3][2][4];
#pragma unroll
    for (int i = 0; i < 3; i++)
#pragma unroll
        for (int j = 0; j < 2; j++)
#pragma unroll
            for (int c = 0; c < 4; c++) acc_o[i][j][c] = 0.f;

    const float scale = 0.125f;

    for (int it = 0; it < AT_NT; it++) {
        int n0 = it * AT_KN;
        int buf = it & 1;
        __syncthreads();   // Qs ready (1st iter); prev-iter PV done -> other buf free

        // prefetch tile it+1 into the other buffer, then wait for tile it
        if (it + 1 < AT_NT) {
            int n1 = n0 + AT_KN;
            int ob = buf ^ 1;
#pragma unroll
            for (int p = 0; p < 2; p++) {
                int r = kv_r0 + p * 32;
                int src = n1 + r; if (src > SEQ - 1) src = SEQ - 1;
                cp16(kbase[ob] + (uint32_t)(r * QK_PW * 4 + kv_ch * 16), ksrc + src * HD + kv_ch * 8);
                cp16(vbase[ob] + (uint32_t)(r * QK_PW * 4 + kv_ch * 16),
                     vsrc + r * SEQ_PAD + n1 + kv_ch * 8);
            }
            CP_COMMIT();
            CP_WAIT(1);
        } else {
            CP_WAIT(0);
        }
        __syncthreads();

        uint32_t* Ks_u = smu + (buf ? AOFF_K1 : AOFF_K0);
        uint32_t* Vs_u = smu + (buf ? AOFF_V1 : AOFF_V0);

        // ---- S = Q K^T, bf16 m16n8k16, 4 k-steps
        float acc_s[3][2][4];
#pragma unroll
        for (int i = 0; i < 3; i++)
#pragma unroll
            for (int j = 0; j < 2; j++)
#pragma unroll
                for (int c = 0; c < 4; c++) acc_s[i][j][c] = 0.f;

#pragma unroll
        for (int ks = 0; ks < 4; ks++) {
            int kb = ks * 8;
            uint32_t af[3][4], bf[2][2];
#pragma unroll
            for (int i = 0; i < 3; i++) {
                int r = warp_m * 48 + i * 16 + g;
                af[i][0] = Qs_u[r * QK_PW + kb + tig];
                af[i][1] = Qs_u[(r + 8) * QK_PW + kb + tig];
                af[i][2] = Qs_u[r * QK_PW + kb + 4 + tig];
                af[i][3] = Qs_u[(r + 8) * QK_PW + kb + 4 + tig];
            }
#pragma unroll
            for (int j = 0; j < 2; j++) {
                int cix = warp_n * 16 + j * 8 + g;
                bf[j][0] = Ks_u[cix * QK_PW + kb + tig];
                bf[j][1] = Ks_u[cix * QK_PW + kb + 4 + tig];
            }
#pragma unroll
            for (int i = 0; i < 3; i++)
#pragma unroll
                for (int j = 0; j < 2; j++)
                    MMA_BF16(acc_s[i][j], af[i], bf[j]);
        }

        // ---- write S*scale (fp32) with key mask
#pragma unroll
        for (int i = 0; i < 3; i++) {
            int r0 = warp_m * 48 + i * 16 + g;
#pragma unroll
            for (int j = 0; j < 2; j++) {
                int c0 = warp_n * 16 + j * 8 + 2 * tig;
                bool v0 = (n0 + c0) < SEQ, v1 = (n0 + c0 + 1) < SEQ;
                Ss[r0 * 68 + c0]           = v0 ? acc_s[i][j][0] * scale : -1e30f;
                Ss[r0 * 68 + c0 + 1]       = v1 ? acc_s[i][j][1] * scale : -1e30f;
                Ss[(r0 + 8) * 68 + c0]     = v0 ? acc_s[i][j][2] * scale : -1e30f;
                Ss[(r0 + 8) * 68 + c0 + 1] = v1 ? acc_s[i][j][3] * scale : -1e30f;
            }
        }
        __syncthreads();

        // ---- row softmax -> Ps bf16
        if (t < AT_M) {
            float* row = Ss + t * 68;
            uint32_t* prow = Ps_u + t * QK_PW;
            float mo = s_m[t], mx = mo;
#pragma unroll
            for (int c4 = 0; c4 < AT_KN; c4 += 4) {
                float4 v = *(float4*)(row + c4);
                mx = fmaxf(mx, fmaxf(fmaxf(v.x, v.y), fmaxf(v.z, v.w)));
            }
            float fac = __expf(mo - mx);
            s_f[t] = fac; s_m[t] = mx;
            float sum = 0.f;
#pragma unroll
            for (int c4 = 0; c4 < AT_KN; c4 += 4) {
                float4 v = *(float4*)(row + c4);
                v.x = __expf(v.x - mx); v.y = __expf(v.y - mx);
                v.z = __expf(v.z - mx); v.w = __expf(v.w - mx);
                sum += v.x + v.y + v.z + v.w;
                prow[c4 / 2]     = packbf(v.x, v.y);
                prow[c4 / 2 + 1] = packbf(v.z, v.w);
            }
            s_l[t] = s_l[t] * fac + sum;
        }
        __syncthreads();

        // ---- rescale O, then O += P V (bf16, 4 k-steps over 64 keys)
#pragma unroll
        for (int i = 0; i < 3; i++) {
            int r0 = warp_m * 48 + i * 16 + g;
            float f0 = s_f[r0], f1 = s_f[r0 + 8];
#pragma unroll
            for (int j = 0; j < 2; j++) {
                acc_o[i][j][0] *= f0; acc_o[i][j][1] *= f0;
                acc_o[i][j][2] *= f1; acc_o[i][j][3] *= f1;
            }
        }
#pragma unroll
        for (int ks = 0; ks < 4; ks++) {
            int kb = ks * 8;
            uint32_t af[3][4], bf[2][2];
#pragma unroll
            for (int i = 0; i < 3; i++) {
                int r = warp_m * 48 + i * 16 + g;
                af[i][0] = Ps_u[r * QK_PW + kb + tig];
                af[i][1] = Ps_u[(r + 8) * QK_PW + kb + tig];
                af[i][2] = Ps_u[r * QK_PW + kb + 4 + tig];
                af[i][3] = Ps_u[(r + 8) * QK_PW + kb + 4 + tig];
            }
#pragma unroll
            for (int j = 0; j < 2; j++) {
                int cix = warp_n * 16 + j * 8 + g;   // output dim d = Vs row
#pragma unroll
                for (int kh = 0; kh < 2; kh++)
                    bf[j][kh] = Vs_u[cix * QK_PW + kb + kh * 4 + tig];
            }
#pragma unroll
            for (int i = 0; i < 3; i++)
#pragma unroll
                for (int j = 0; j < 2; j++)
                    MMA_BF16(acc_o[i][j], af[i], bf[j]);
        }
    }
    __syncthreads();

    // ---- writeout: g_att[b*78 + r][h*64 + c] = O / l  (fp32)
#pragma unroll
    for (int i = 0; i < 3; i++) {
        int r0 = warp_m * 48 + i * 16 + g;
#pragma unroll
        for (int half = 0; half < 2; half++) {
            int r = r0 + half * 8;
            if (r >= NLOC) continue;
            float inv = 1.f / s_l[r];
            float* dst = g_att + ((size_t)(b * NLOC + r)) * CDIM + h * HD;
#pragma unroll
            for (int j = 0; j < 2; j++) {
                int c0 = warp_n * 16 + j * 8 + 2 * tig;
                float2 o;
                o.x = acc_o[i][j][half * 2 + 0] * inv;
                o.y = acc_o[i][j][half * 2 + 1] * inv;
                *(float2*)(dst + c0) = o;
            }
        }
    }
}

// ---------------- launch ---------------------------------------------------
extern "C" void kernel_launch(void* const* d_in, const int* in_sizes, int n_in,
                              void* d_out, int out_size)
{
    const float* x    = (const float*)d_in[0];
    const float* roll = (const float*)d_in[1];
    const float* Wq   = (const float*)d_in[2];
    const float* bq   = (const float*)d_in[3];
    const float* Wkv  = (const float*)d_in[4];
    const float* bkv  = (const float*)d_in[5];
    const float* Wp   = (const float*)d_in[6];
    const float* bp   = (const float*)d_in[7];
    float* out = (float*)d_out;

    const int attn_smem = AT_SMEM_U32 * 4;

    static int s_attr_done = 0;
    if (!s_attr_done) {
        cudaFuncSetAttribute(attn_kernel,
                             cudaFuncAttributeMaxDynamicSharedMemorySize, attn_smem);
        cudaFuncSetAttribute(gemm_bf16<0>,
                             cudaFuncAttributeMaxDynamicSharedMemorySize, BF_SMEM_BYTES);
        cudaFuncSetAttribute(gemm_bf16<1>,
                             cudaFuncAttributeMaxDynamicSharedMemorySize, BF_SMEM_BYTES);
        cudaFuncSetAttribute(gemm_tf32_out,
                             cudaFuncAttributeMaxDynamicSharedMemorySize, G_SMEM_BYTES);
        s_attr_done = 1;
    }

    // fused pass-through copy + x->bf16 conversion
    copyconv_x_kernel<<<1024, 256>>>(x, out);

    // weight conversions
    __nv_bfloat16 *wkv_bt, *wq_bt;
    cudaGetSymbolAddress((void**)&wkv_bt, g_Wkv_bt);
    cudaGetSymbolAddress((void**)&wq_bt,  g_Wq_bt);
    convt_kernel<<<dim3(2 * CDIM / 32, CDIM / 32), dim3(32, 8)>>>(Wkv, wkv_bt, CDIM, 2 * CDIM);
    convt_kernel<<<dim3(CDIM / 32, CDIM / 32), dim3(32, 8)>>>(Wq, wq_bt, CDIM, CDIM);

    // top-k indices per batch
    topk_kernel<<<NB, 1024>>>(roll);

    // KV projection (bf16, 256x128 tiles): [50240,768] @ [768,1536]
    {
        int M = NB * SEQ;
        dim3 grid((2 * CDIM) / 128, (M + 255) / 256);
        gemm_bf16<0><<<grid, 256, BF_SMEM_BYTES>>>(bkv);
    }
    // Q projection (bf16, gathered rows): [4992,768] @ [768,768]
    {
        int M = NB * NLOC;
        dim3 grid(CDIM / 128, (M + 255) / 256);
        gemm_bf16<1><<<grid, 256, BF_SMEM_BYTES>>>(bq);
    }
    // fused bf16 attention (double-buffered K/V) -> g_att
    attn_kernel<<<NB * NH, 256, attn_smem>>>();

    // output projection (tf32) + scatter into out
    {
        int M = NB * NLOC;
        dim3 grid(CDIM / 128, (M + 127) / 128);
        gemm_tf32_out<<<grid, 256, G_SMEM_BYTES>>>(Wp, bp, out);
    }
}